// round 8
// baseline (speedup 1.0000x reference)
#include <cuda_runtime.h>
#include <cstdint>

#define N_NODES 50000
#define N_EDGES 1600000
#define F_INDIM 128
#define HID     64
#define NCLS    19
#define NGRAPH  512
#define SBLK    256
#define NSBLK   ((N_NODES + SBLK - 1) / SBLK)   // 196

// ---- scratch (static device globals; no allocation) ----
__device__ int   g_ecnt[N_NODES];
__device__ int   g_off [N_NODES + 1];
__device__ int   g_cur [N_NODES];
__device__ int   g_part[NSBLK];
__device__ int2  g_edge[N_EDGES];         // packed (src, __float_as_int(norm))
__device__ float g_dinv[N_NODES];
__device__ float g_a   [N_NODES * HID];   // gemm output / gather source
__device__ float g_b   [N_NODES * HID];   // layer-1 aggregation output
__device__ float g_pool[NGRAPH * HID];
__device__ float g_cnt [NGRAPH];

__device__ __forceinline__ void red_add_v4(float* addr, float4 v) {
    asm volatile("red.global.add.v4.f32 [%0], {%1, %2, %3, %4};"
                 :: "l"(addr), "f"(v.x), "f"(v.y), "f"(v.z), "f"(v.w)
                 : "memory");
}

// ---------------------------------------------------------------------------
__global__ void k_init() {
    int i = blockIdx.x * blockDim.x + threadIdx.x;
    if (i < N_NODES)       g_ecnt[i] = 0;
    if (i < NGRAPH * HID)  g_pool[i] = 0.f;
    if (i < NGRAPH)        g_cnt[i]  = 0.f;
}

__global__ void k_count(const int* __restrict__ ei) {
    int e = blockIdx.x * blockDim.x + threadIdx.x;
    if (e < N_EDGES) atomicAdd(&g_ecnt[ei[N_EDGES + e]], 1);
}

__global__ void k_dinv_cnt(const int* __restrict__ batch) {
    int i = blockIdx.x * blockDim.x + threadIdx.x;
    if (i < N_NODES) {
        g_dinv[i] = rsqrtf(1.0f + (float)g_ecnt[i]);   // +1 self-loop
        atomicAdd(&g_cnt[batch[i]], 1.0f);
    }
}

// ---- 3-phase multi-block exclusive scan of g_ecnt into g_off/g_cur --------
__global__ void k_scan1() {
    __shared__ int sh[SBLK];
    const int t = threadIdx.x;
    const int i = blockIdx.x * SBLK + t;
    int v = (i < N_NODES) ? g_ecnt[i] : 0;
    sh[t] = v;
    __syncthreads();
    #pragma unroll
    for (int off = 1; off < SBLK; off <<= 1) {
        int u = (t >= off) ? sh[t - off] : 0;
        __syncthreads();
        if (t >= off) sh[t] += u;
        __syncthreads();
    }
    if (i < N_NODES) g_off[i] = sh[t] - v;
    if (t == SBLK - 1) g_part[blockIdx.x] = sh[t];
}

__global__ void k_scan2() {
    __shared__ int sh[SBLK];
    const int t = threadIdx.x;
    int v = (t < NSBLK) ? g_part[t] : 0;
    sh[t] = v;
    __syncthreads();
    #pragma unroll
    for (int off = 1; off < SBLK; off <<= 1) {
        int u = (t >= off) ? sh[t - off] : 0;
        __syncthreads();
        if (t >= off) sh[t] += u;
        __syncthreads();
    }
    if (t < NSBLK) g_part[t] = sh[t] - v;
    if (t == SBLK - 1) g_off[N_NODES] = sh[t];
}

__global__ void k_scan3() {
    const int i = blockIdx.x * SBLK + threadIdx.x;
    if (i < N_NODES) {
        int o = g_off[i] + g_part[blockIdx.x];
        g_off[i] = o;
        g_cur[i] = o;
    }
}

__global__ void k_scatter(const int* __restrict__ ei) {
    int e = blockIdx.x * blockDim.x + threadIdx.x;
    if (e >= N_EDGES) return;
    int s = ei[e];
    int d = ei[N_EDGES + e];
    int pos = atomicAdd(&g_cur[d], 1);
    g_edge[pos] = make_int2(s, __float_as_int(g_dinv[s] * g_dinv[d]));
}

// ---------------------------------------------------------------------------
// Register-tiled GEMM: out[n, 64] = act(X[n, K]) @ W[K, 64]
// 128 threads/block, 64 nodes/block; thread tile = 8 nodes x 4 cols.
// Per 4-k step: 12 float4 LDS for 128 FMAs (1.5 B/FMA) -> FFMA-bound.
template <int K, bool BIAS_RELU>
__global__ void k_gemm_fused(const float* X, const float* __restrict__ W,
                             const float* __restrict__ bias, float* out) {
    constexpr int XP = K + 4;
    __shared__ float Xs[64 * XP];
    __shared__ float Ws[K * HID];
    const int tid = threadIdx.x;          // 0..127
    const int nb  = blockIdx.x * 64;

    for (int i = tid; i < K * HID; i += 128) Ws[i] = W[i];
    for (int i = tid; i < 64 * K; i += 128) {
        int nl = i / K, k = i % K;
        int node = nb + nl;
        float v = (node < N_NODES) ? X[node * K + k] : 0.0f;
        if (BIAS_RELU) { v += bias[k]; v = v > 0.f ? v : 0.f; }
        Xs[nl * XP + k] = v;
    }
    __syncthreads();

    const int ny0 = (tid >> 4) * 8;       // 8 local nodes
    const int c0  = (tid & 15) * 4;       // 4 output cols

    float4 acc[8];
    #pragma unroll
    for (int i = 0; i < 8; ++i) acc[i] = make_float4(0.f, 0.f, 0.f, 0.f);

    #pragma unroll 2
    for (int k = 0; k < K; k += 4) {
        float4 wr[4];
        #pragma unroll
        for (int j = 0; j < 4; ++j)
            wr[j] = *reinterpret_cast<const float4*>(&Ws[(k + j) * HID + c0]);
        #pragma unroll
        for (int i = 0; i < 8; ++i) {
            float4 xr = *reinterpret_cast<const float4*>(&Xs[(ny0 + i) * XP + k]);
            acc[i].x += xr.x*wr[0].x + xr.y*wr[1].x + xr.z*wr[2].x + xr.w*wr[3].x;
            acc[i].y += xr.x*wr[0].y + xr.y*wr[1].y + xr.z*wr[2].y + xr.w*wr[3].y;
            acc[i].z += xr.x*wr[0].z + xr.y*wr[1].z + xr.z*wr[2].z + xr.w*wr[3].z;
            acc[i].w += xr.x*wr[0].w + xr.y*wr[1].w + xr.z*wr[2].w + xr.w*wr[3].w;
        }
    }

    #pragma unroll
    for (int i = 0; i < 8; ++i) {
        int node = nb + ny0 + i;
        if (node >= N_NODES) break;
        *reinterpret_cast<float4*>(&out[node * HID + c0]) = acc[i];
    }
}

// ---------------------------------------------------------------------------
// CSR aggregation, float4 lanes: 16 threads own one node, lane l owns
// features [4l, 4l+4). One int2 load per edge gives (src, norm).
template <bool POOL>
__global__ void k_agg_csr(const int* __restrict__ batch) {
    const int node = blockIdx.x * 16 + (threadIdx.x >> 4);
    const int c0   = (threadIdx.x & 15) * 4;
    if (node >= N_NODES) return;

    float dn = g_dinv[node]; dn *= dn;
    float4 acc = *reinterpret_cast<const float4*>(&g_a[node * HID + c0]);
    acc.x *= dn; acc.y *= dn; acc.z *= dn; acc.w *= dn;

    const int beg = g_off[node];
    const int end = g_off[node + 1];
    int e = beg;
    for (; e + 2 <= end; e += 2) {
        int2 e0 = g_edge[e], e1 = g_edge[e + 1];
        float n0 = __int_as_float(e0.y), n1 = __int_as_float(e1.y);
        float4 v0 = *reinterpret_cast<const float4*>(&g_a[e0.x * HID + c0]);
        float4 v1 = *reinterpret_cast<const float4*>(&g_a[e1.x * HID + c0]);
        acc.x += n0 * v0.x + n1 * v1.x;
        acc.y += n0 * v0.y + n1 * v1.y;
        acc.z += n0 * v0.z + n1 * v1.z;
        acc.w += n0 * v0.w + n1 * v1.w;
    }
    if (e < end) {
        int2 e0 = g_edge[e];
        float n0 = __int_as_float(e0.y);
        float4 v0 = *reinterpret_cast<const float4*>(&g_a[e0.x * HID + c0]);
        acc.x += n0 * v0.x; acc.y += n0 * v0.y;
        acc.z += n0 * v0.z; acc.w += n0 * v0.w;
    }

    if (POOL) {
        int g = batch[node];
        red_add_v4(&g_pool[g * HID + c0], acc);
    } else {
        *reinterpret_cast<float4*>(&g_b[node * HID + c0]) = acc;
    }
}

// Warp per graph: out[g, c] = (mean(pool) + b2) @ W_out + b_out
__global__ void k_final(const float* __restrict__ b2,
                        const float* __restrict__ Wout,
                        const float* __restrict__ bout,
                        float* __restrict__ out) {
    int gt   = blockIdx.x * blockDim.x + threadIdx.x;
    int g    = gt >> 5;
    int lane = gt & 31;
    if (g >= NGRAPH || lane >= NCLS) return;
    float cnt = g_cnt[g];
    float inv = cnt > 0.f ? 1.0f / cnt : 0.0f;
    float has = cnt > 0.f ? 1.0f : 0.0f;
    float acc = bout[lane];
    #pragma unroll
    for (int h = 0; h < HID; ++h) {
        float ph = g_pool[g * HID + h] * inv + has * b2[h];
        acc += ph * Wout[h * NCLS + lane];
    }
    out[g * NCLS + lane] = acc;
}

// ---------------------------------------------------------------------------
extern "C" void kernel_launch(void* const* d_in, const int* in_sizes, int n_in,
                              void* d_out, int out_size) {
    const float* x    = (const float*)d_in[0];
    const int*   ei   = (const int*)  d_in[1];   // int32 (JAX x64 disabled)
    const int*   bat  = (const int*)  d_in[2];
    const float* W1   = (const float*)d_in[3];
    const float* b1   = (const float*)d_in[4];
    const float* W2   = (const float*)d_in[5];
    const float* b2   = (const float*)d_in[6];
    const float* Wout = (const float*)d_in[7];
    const float* bout = (const float*)d_in[8];
    float* out = (float*)d_out;

    float* pa;  cudaGetSymbolAddress((void**)&pa, g_a);
    float* pb;  cudaGetSymbolAddress((void**)&pb, g_b);

    const int TB = 256;
    const int initN  = (N_NODES > NGRAPH * HID) ? N_NODES : NGRAPH * HID;
    const int nblkI  = (initN + TB - 1) / TB;
    const int nblkN  = (N_NODES + TB - 1) / TB;
    const int nblkE  = (N_EDGES + TB - 1) / TB;
    const int nblkG  = (N_NODES + 63) / 64;
    const int nblkAg = (N_NODES + 15) / 16;

    // CSR build (once per call; reused by both layers)
    k_init    <<<nblkI, TB>>>();
    k_count   <<<nblkE, TB>>>(ei);
    k_dinv_cnt<<<nblkN, TB>>>(bat);
    k_scan1   <<<NSBLK, SBLK>>>();
    k_scan2   <<<1, SBLK>>>();
    k_scan3   <<<NSBLK, SBLK>>>();
    k_scatter <<<nblkE, TB>>>(ei);

    // layer 1
    k_gemm_fused<F_INDIM, false><<<nblkG, 128>>>(x, W1, nullptr, pa);
    k_agg_csr<false><<<nblkAg, TB>>>(bat);

    // layer 2 (relu + b1 fused into gemm input; pool fused into agg)
    k_gemm_fused<HID, true><<<nblkG, 128>>>(pb, W2, b1, pa);
    k_agg_csr<true><<<nblkAg, TB>>>(bat);

    // linear head (b2 folded in)
    k_final<<<(NGRAPH * 32 + TB - 1) / TB, TB>>>(b2, Wout, bout, out);
}

// round 9
// speedup vs baseline: 1.4150x; 1.4150x over previous
#include <cuda_runtime.h>
#include <cstdint>

#define N_NODES 50000
#define N_EDGES 1600000
#define F_INDIM 128
#define HID     64
#define NCLS    19
#define NGRAPH  512
#define SBLK    256
#define NSBLK   ((N_NODES + SBLK - 1) / SBLK)   // 196

// ---- scratch (static device globals; no allocation) ----
__device__ int   g_ecnt[N_NODES];
__device__ int   g_off [N_NODES + 1];
__device__ int   g_cur [N_NODES];
__device__ int   g_part[NSBLK];
__device__ int2  g_edge[N_EDGES];         // packed (src, __float_as_int(norm))
__device__ float g_dinv[N_NODES];
__device__ float g_a   [N_NODES * HID];   // gemm output / gather source
__device__ float g_b   [N_NODES * HID];   // layer-1 aggregation output
__device__ float g_pool[NGRAPH * HID];
__device__ float g_cnt [NGRAPH];

__device__ __forceinline__ void red_add_v4(float* addr, float4 v) {
    asm volatile("red.global.add.v4.f32 [%0], {%1, %2, %3, %4};"
                 :: "l"(addr), "f"(v.x), "f"(v.y), "f"(v.z), "f"(v.w)
                 : "memory");
}

// ---------------------------------------------------------------------------
__global__ void k_init() {
    int i = blockIdx.x * blockDim.x + threadIdx.x;
    if (i < N_NODES)       g_ecnt[i] = 0;
    if (i < NGRAPH * HID)  g_pool[i] = 0.f;
    if (i < NGRAPH)        g_cnt[i]  = 0.f;
}

__global__ void k_count(const int* __restrict__ ei) {
    int e = blockIdx.x * blockDim.x + threadIdx.x;
    if (e < N_EDGES) atomicAdd(&g_ecnt[ei[N_EDGES + e]], 1);
}

__global__ void k_dinv_cnt(const int* __restrict__ batch) {
    int i = blockIdx.x * blockDim.x + threadIdx.x;
    if (i < N_NODES) {
        g_dinv[i] = rsqrtf(1.0f + (float)g_ecnt[i]);   // +1 self-loop
        atomicAdd(&g_cnt[batch[i]], 1.0f);
    }
}

// ---- 3-phase multi-block exclusive scan of g_ecnt into g_off/g_cur --------
__global__ void k_scan1() {
    __shared__ int sh[SBLK];
    const int t = threadIdx.x;
    const int i = blockIdx.x * SBLK + t;
    int v = (i < N_NODES) ? g_ecnt[i] : 0;
    sh[t] = v;
    __syncthreads();
    #pragma unroll
    for (int off = 1; off < SBLK; off <<= 1) {
        int u = (t >= off) ? sh[t - off] : 0;
        __syncthreads();
        if (t >= off) sh[t] += u;
        __syncthreads();
    }
    if (i < N_NODES) g_off[i] = sh[t] - v;
    if (t == SBLK - 1) g_part[blockIdx.x] = sh[t];
}

__global__ void k_scan2() {
    __shared__ int sh[SBLK];
    const int t = threadIdx.x;
    int v = (t < NSBLK) ? g_part[t] : 0;
    sh[t] = v;
    __syncthreads();
    #pragma unroll
    for (int off = 1; off < SBLK; off <<= 1) {
        int u = (t >= off) ? sh[t - off] : 0;
        __syncthreads();
        if (t >= off) sh[t] += u;
        __syncthreads();
    }
    if (t < NSBLK) g_part[t] = sh[t] - v;
    if (t == SBLK - 1) g_off[N_NODES] = sh[t];
}

__global__ void k_scan3() {
    const int i = blockIdx.x * SBLK + threadIdx.x;
    if (i < N_NODES) {
        int o = g_off[i] + g_part[blockIdx.x];
        g_off[i] = o;
        g_cur[i] = o;
    }
}

__global__ void k_scatter(const int* __restrict__ ei) {
    int e = blockIdx.x * blockDim.x + threadIdx.x;
    if (e >= N_EDGES) return;
    int s = ei[e];
    int d = ei[N_EDGES + e];
    int pos = atomicAdd(&g_cur[d], 1);
    g_edge[pos] = make_int2(s, __float_as_int(g_dinv[s] * g_dinv[d]));
}

// ---------------------------------------------------------------------------
// Register-tiled GEMM: out[n, 64] = act(X[n, K]) @ W[K, 64]
// R7-proven shape: 256 threads/block, 64 nodes; thread tile = 4 nodes x 4 cols.
template <int K, bool BIAS_RELU>
__global__ void k_gemm_fused(const float* X, const float* __restrict__ W,
                             const float* __restrict__ bias, float* out) {
    constexpr int XP = K + 4;
    __shared__ float Xs[64 * XP];
    __shared__ float Ws[K * HID];
    const int tid = threadIdx.x;
    const int nb  = blockIdx.x * 64;

    for (int i = tid; i < K * HID; i += 256) Ws[i] = W[i];
    for (int i = tid; i < 64 * K; i += 256) {
        int nl = i / K, k = i % K;
        int node = nb + nl;
        float v = (node < N_NODES) ? X[node * K + k] : 0.0f;
        if (BIAS_RELU) { v += bias[k]; v = v > 0.f ? v : 0.f; }
        Xs[nl * XP + k] = v;
    }
    __syncthreads();

    const int ny0 = (tid / 16) * 4;
    const int c0  = (tid & 15) * 4;

    float4 acc[4];
    #pragma unroll
    for (int i = 0; i < 4; ++i) acc[i] = make_float4(0.f, 0.f, 0.f, 0.f);

    #pragma unroll 4
    for (int k = 0; k < K; k += 4) {
        float4 xr[4], wr[4];
        #pragma unroll
        for (int i = 0; i < 4; ++i)
            xr[i] = *reinterpret_cast<const float4*>(&Xs[(ny0 + i) * XP + k]);
        #pragma unroll
        for (int j = 0; j < 4; ++j)
            wr[j] = *reinterpret_cast<const float4*>(&Ws[(k + j) * HID + c0]);
        #pragma unroll
        for (int i = 0; i < 4; ++i) {
            const float x0 = xr[i].x, x1 = xr[i].y, x2 = xr[i].z, x3 = xr[i].w;
            acc[i].x += x0*wr[0].x + x1*wr[1].x + x2*wr[2].x + x3*wr[3].x;
            acc[i].y += x0*wr[0].y + x1*wr[1].y + x2*wr[2].y + x3*wr[3].y;
            acc[i].z += x0*wr[0].z + x1*wr[1].z + x2*wr[2].z + x3*wr[3].z;
            acc[i].w += x0*wr[0].w + x1*wr[1].w + x2*wr[2].w + x3*wr[3].w;
        }
    }

    #pragma unroll
    for (int i = 0; i < 4; ++i) {
        int node = nb + ny0 + i;
        if (node >= N_NODES) break;
        *reinterpret_cast<float4*>(&out[node * HID + c0]) = acc[i];
    }
}

// ---------------------------------------------------------------------------
// CSR aggregation, float4 lanes: 16 threads own one node, lane l owns
// features [4l, 4l+4). One int2 load per edge gives (src, norm).
template <bool POOL>
__global__ void k_agg_csr(const int* __restrict__ batch) {
    const int node = blockIdx.x * 16 + (threadIdx.x >> 4);
    const int c0   = (threadIdx.x & 15) * 4;
    if (node >= N_NODES) return;

    float dn = g_dinv[node]; dn *= dn;
    float4 acc = *reinterpret_cast<const float4*>(&g_a[node * HID + c0]);
    acc.x *= dn; acc.y *= dn; acc.z *= dn; acc.w *= dn;

    const int beg = g_off[node];
    const int end = g_off[node + 1];
    int e = beg;
    for (; e + 2 <= end; e += 2) {
        int2 e0 = g_edge[e], e1 = g_edge[e + 1];
        float n0 = __int_as_float(e0.y), n1 = __int_as_float(e1.y);
        float4 v0 = *reinterpret_cast<const float4*>(&g_a[e0.x * HID + c0]);
        float4 v1 = *reinterpret_cast<const float4*>(&g_a[e1.x * HID + c0]);
        acc.x += n0 * v0.x + n1 * v1.x;
        acc.y += n0 * v0.y + n1 * v1.y;
        acc.z += n0 * v0.z + n1 * v1.z;
        acc.w += n0 * v0.w + n1 * v1.w;
    }
    if (e < end) {
        int2 e0 = g_edge[e];
        float n0 = __int_as_float(e0.y);
        float4 v0 = *reinterpret_cast<const float4*>(&g_a[e0.x * HID + c0]);
        acc.x += n0 * v0.x; acc.y += n0 * v0.y;
        acc.z += n0 * v0.z; acc.w += n0 * v0.w;
    }

    if (POOL) {
        int g = batch[node];
        red_add_v4(&g_pool[g * HID + c0], acc);
    } else {
        *reinterpret_cast<float4*>(&g_b[node * HID + c0]) = acc;
    }
}

// Warp per graph: out[g, c] = (mean(pool) + b2) @ W_out + b_out
__global__ void k_final(const float* __restrict__ b2,
                        const float* __restrict__ Wout,
                        const float* __restrict__ bout,
                        float* __restrict__ out) {
    int gt   = blockIdx.x * blockDim.x + threadIdx.x;
    int g    = gt >> 5;
    int lane = gt & 31;
    if (g >= NGRAPH || lane >= NCLS) return;
    float cnt = g_cnt[g];
    float inv = cnt > 0.f ? 1.0f / cnt : 0.0f;
    float has = cnt > 0.f ? 1.0f : 0.0f;
    float acc = bout[lane];
    #pragma unroll
    for (int h = 0; h < HID; ++h) {
        float ph = g_pool[g * HID + h] * inv + has * b2[h];
        acc += ph * Wout[h * NCLS + lane];
    }
    out[g * NCLS + lane] = acc;
}

// ---------------------------------------------------------------------------
extern "C" void kernel_launch(void* const* d_in, const int* in_sizes, int n_in,
                              void* d_out, int out_size) {
    const float* x    = (const float*)d_in[0];
    const int*   ei   = (const int*)  d_in[1];   // int32 (JAX x64 disabled)
    const int*   bat  = (const int*)  d_in[2];
    const float* W1   = (const float*)d_in[3];
    const float* b1   = (const float*)d_in[4];
    const float* W2   = (const float*)d_in[5];
    const float* b2   = (const float*)d_in[6];
    const float* Wout = (const float*)d_in[7];
    const float* bout = (const float*)d_in[8];
    float* out = (float*)d_out;

    float* pa;  cudaGetSymbolAddress((void**)&pa, g_a);
    float* pb;  cudaGetSymbolAddress((void**)&pb, g_b);

    const int TB = 256;
    const int initN  = (N_NODES > NGRAPH * HID) ? N_NODES : NGRAPH * HID;
    const int nblkI  = (initN + TB - 1) / TB;
    const int nblkN  = (N_NODES + TB - 1) / TB;
    const int nblkE  = (N_EDGES + TB - 1) / TB;
    const int nblkG  = (N_NODES + 63) / 64;
    const int nblkAg = (N_NODES + 15) / 16;

    // CSR build (once per call; reused by both layers)
    k_init    <<<nblkI, TB>>>();
    k_count   <<<nblkE, TB>>>(ei);
    k_dinv_cnt<<<nblkN, TB>>>(bat);
    k_scan1   <<<NSBLK, SBLK>>>();
    k_scan2   <<<1, SBLK>>>();
    k_scan3   <<<NSBLK, SBLK>>>();
    k_scatter <<<nblkE, TB>>>(ei);

    // layer 1
    k_gemm_fused<F_INDIM, false><<<nblkG, TB>>>(x, W1, nullptr, pa);
    k_agg_csr<false><<<nblkAg, TB>>>(bat);

    // layer 2 (relu + b1 fused into gemm input; pool fused into agg)
    k_gemm_fused<HID, true><<<nblkG, TB>>>(pb, W2, b1, pa);
    k_agg_csr<true><<<nblkAg, TB>>>(bat);

    // linear head (b2 folded in)
    k_final<<<(NGRAPH * 32 + TB - 1) / TB, TB>>>(b2, Wout, bout, out);
}

// round 10
// speedup vs baseline: 1.5403x; 1.0886x over previous
#include <cuda_runtime.h>
#include <cstdint>

#define N_NODES 50000
#define N_EDGES 1600000
#define F_INDIM 128
#define HID     64
#define NCLS    19
#define NGRAPH  512
#define SBLK    256
#define NSBLK   ((N_NODES + SBLK - 1) / SBLK)   // 196

// ---- scratch (static device globals; no allocation) ----
__device__ int   g_ecnt[N_NODES];
__device__ int   g_off [N_NODES + 1];
__device__ int   g_cur [N_NODES];
__device__ int   g_part[NSBLK];
__device__ int2  g_edge[N_EDGES];         // packed (src, __float_as_int(norm))
__device__ float g_dinv[N_NODES];
__device__ float g_a   [N_NODES * HID];   // gemm output / gather source
__device__ float g_b   [N_NODES * HID];   // layer-1 aggregation output
__device__ float g_pool[NGRAPH * HID];
__device__ float g_cnt [NGRAPH];

__device__ __forceinline__ void red_add_v4(float* addr, float4 v) {
    asm volatile("red.global.add.v4.f32 [%0], {%1, %2, %3, %4};"
                 :: "l"(addr), "f"(v.x), "f"(v.y), "f"(v.z), "f"(v.w)
                 : "memory");
}

// ---------------------------------------------------------------------------
__global__ void k_init() {
    int i = blockIdx.x * blockDim.x + threadIdx.x;
    if (i < N_NODES)       g_ecnt[i] = 0;
    if (i < NGRAPH * HID)  g_pool[i] = 0.f;
    if (i < NGRAPH)        g_cnt[i]  = 0.f;
}

__global__ void k_count(const int* __restrict__ ei) {
    int e = blockIdx.x * blockDim.x + threadIdx.x;
    if (e < N_EDGES) atomicAdd(&g_ecnt[ei[N_EDGES + e]], 1);
}

// ---- scan phase 1, with dinv + per-graph node count folded in -------------
__global__ void k_scan1(const int* __restrict__ batch) {
    __shared__ int sh[SBLK];
    const int t = threadIdx.x;
    const int i = blockIdx.x * SBLK + t;
    int v = (i < N_NODES) ? g_ecnt[i] : 0;
    if (i < N_NODES) {
        g_dinv[i] = rsqrtf(1.0f + (float)v);           // +1 self-loop
        atomicAdd(&g_cnt[batch[i]], 1.0f);
    }
    sh[t] = v;
    __syncthreads();
    #pragma unroll
    for (int off = 1; off < SBLK; off <<= 1) {
        int u = (t >= off) ? sh[t - off] : 0;
        __syncthreads();
        if (t >= off) sh[t] += u;
        __syncthreads();
    }
    if (i < N_NODES) g_off[i] = sh[t] - v;
    if (t == SBLK - 1) g_part[blockIdx.x] = sh[t];
}

__global__ void k_scan2() {
    __shared__ int sh[SBLK];
    const int t = threadIdx.x;
    int v = (t < NSBLK) ? g_part[t] : 0;
    sh[t] = v;
    __syncthreads();
    #pragma unroll
    for (int off = 1; off < SBLK; off <<= 1) {
        int u = (t >= off) ? sh[t - off] : 0;
        __syncthreads();
        if (t >= off) sh[t] += u;
        __syncthreads();
    }
    if (t < NSBLK) g_part[t] = sh[t] - v;
    if (t == SBLK - 1) g_off[N_NODES] = sh[t];
}

__global__ void k_scan3() {
    const int i = blockIdx.x * SBLK + threadIdx.x;
    if (i < N_NODES) {
        int o = g_off[i] + g_part[blockIdx.x];
        g_off[i] = o;
        g_cur[i] = o;
    }
}

__global__ void k_scatter(const int* __restrict__ ei) {
    int e = blockIdx.x * blockDim.x + threadIdx.x;
    if (e >= N_EDGES) return;
    int s = ei[e];
    int d = ei[N_EDGES + e];
    int pos = atomicAdd(&g_cur[d], 1);
    g_edge[pos] = make_int2(s, __float_as_int(g_dinv[s] * g_dinv[d]));
}

// ---------------------------------------------------------------------------
// Register-tiled GEMM (protected R7 shape): 256 thr, 64 nodes, 4x4 tile.
template <int K, bool BIAS_RELU>
__global__ void k_gemm_fused(const float* X, const float* __restrict__ W,
                             const float* __restrict__ bias, float* out) {
    constexpr int XP = K + 4;
    __shared__ float Xs[64 * XP];
    __shared__ float Ws[K * HID];
    const int tid = threadIdx.x;
    const int nb  = blockIdx.x * 64;

    for (int i = tid; i < K * HID; i += 256) Ws[i] = W[i];
    for (int i = tid; i < 64 * K; i += 256) {
        int nl = i / K, k = i % K;
        int node = nb + nl;
        float v = (node < N_NODES) ? X[node * K + k] : 0.0f;
        if (BIAS_RELU) { v += bias[k]; v = v > 0.f ? v : 0.f; }
        Xs[nl * XP + k] = v;
    }
    __syncthreads();

    const int ny0 = (tid / 16) * 4;
    const int c0  = (tid & 15) * 4;

    float4 acc[4];
    #pragma unroll
    for (int i = 0; i < 4; ++i) acc[i] = make_float4(0.f, 0.f, 0.f, 0.f);

    #pragma unroll 4
    for (int k = 0; k < K; k += 4) {
        float4 xr[4], wr[4];
        #pragma unroll
        for (int i = 0; i < 4; ++i)
            xr[i] = *reinterpret_cast<const float4*>(&Xs[(ny0 + i) * XP + k]);
        #pragma unroll
        for (int j = 0; j < 4; ++j)
            wr[j] = *reinterpret_cast<const float4*>(&Ws[(k + j) * HID + c0]);
        #pragma unroll
        for (int i = 0; i < 4; ++i) {
            const float x0 = xr[i].x, x1 = xr[i].y, x2 = xr[i].z, x3 = xr[i].w;
            acc[i].x += x0*wr[0].x + x1*wr[1].x + x2*wr[2].x + x3*wr[3].x;
            acc[i].y += x0*wr[0].y + x1*wr[1].y + x2*wr[2].y + x3*wr[3].y;
            acc[i].z += x0*wr[0].z + x1*wr[1].z + x2*wr[2].z + x3*wr[3].z;
            acc[i].w += x0*wr[0].w + x1*wr[1].w + x2*wr[2].w + x3*wr[3].w;
        }
    }

    #pragma unroll
    for (int i = 0; i < 4; ++i) {
        int node = nb + ny0 + i;
        if (node >= N_NODES) break;
        *reinterpret_cast<float4*>(&out[node * HID + c0]) = acc[i];
    }
}

// ---------------------------------------------------------------------------
// CSR aggregation, float4 lanes: 16 threads per node.
template <bool POOL>
__global__ void k_agg_csr(const int* __restrict__ batch) {
    const int node = blockIdx.x * 16 + (threadIdx.x >> 4);
    const int c0   = (threadIdx.x & 15) * 4;
    if (node >= N_NODES) return;

    float dn = g_dinv[node]; dn *= dn;
    float4 acc = *reinterpret_cast<const float4*>(&g_a[node * HID + c0]);
    acc.x *= dn; acc.y *= dn; acc.z *= dn; acc.w *= dn;

    const int beg = g_off[node];
    const int end = g_off[node + 1];
    int e = beg;
    for (; e + 2 <= end; e += 2) {
        int2 e0 = g_edge[e], e1 = g_edge[e + 1];
        float n0 = __int_as_float(e0.y), n1 = __int_as_float(e1.y);
        float4 v0 = *reinterpret_cast<const float4*>(&g_a[e0.x * HID + c0]);
        float4 v1 = *reinterpret_cast<const float4*>(&g_a[e1.x * HID + c0]);
        acc.x += n0 * v0.x + n1 * v1.x;
        acc.y += n0 * v0.y + n1 * v1.y;
        acc.z += n0 * v0.z + n1 * v1.z;
        acc.w += n0 * v0.w + n1 * v1.w;
    }
    if (e < end) {
        int2 e0 = g_edge[e];
        float n0 = __int_as_float(e0.y);
        float4 v0 = *reinterpret_cast<const float4*>(&g_a[e0.x * HID + c0]);
        acc.x += n0 * v0.x; acc.y += n0 * v0.y;
        acc.z += n0 * v0.z; acc.w += n0 * v0.w;
    }

    if (POOL) {
        int g = batch[node];
        red_add_v4(&g_pool[g * HID + c0], acc);
    } else {
        *reinterpret_cast<float4*>(&g_b[node * HID + c0]) = acc;
    }
}

// Warp per graph: out[g, c] = (mean(pool) + b2) @ W_out + b_out
__global__ void k_final(const float* __restrict__ b2,
                        const float* __restrict__ Wout,
                        const float* __restrict__ bout,
                        float* __restrict__ out) {
    int gt   = blockIdx.x * blockDim.x + threadIdx.x;
    int g    = gt >> 5;
    int lane = gt & 31;
    if (g >= NGRAPH || lane >= NCLS) return;
    float cnt = g_cnt[g];
    float inv = cnt > 0.f ? 1.0f / cnt : 0.0f;
    float has = cnt > 0.f ? 1.0f : 0.0f;
    float acc = bout[lane];
    #pragma unroll
    for (int h = 0; h < HID; ++h) {
        float ph = g_pool[g * HID + h] * inv + has * b2[h];
        acc += ph * Wout[h * NCLS + lane];
    }
    out[g * NCLS + lane] = acc;
}

// ---------------------------------------------------------------------------
extern "C" void kernel_launch(void* const* d_in, const int* in_sizes, int n_in,
                              void* d_out, int out_size) {
    const float* x    = (const float*)d_in[0];
    const int*   ei   = (const int*)  d_in[1];   // int32 (JAX x64 disabled)
    const int*   bat  = (const int*)  d_in[2];
    const float* W1   = (const float*)d_in[3];
    const float* b1   = (const float*)d_in[4];
    const float* W2   = (const float*)d_in[5];
    const float* b2   = (const float*)d_in[6];
    const float* Wout = (const float*)d_in[7];
    const float* bout = (const float*)d_in[8];
    float* out = (float*)d_out;

    float* pa;  cudaGetSymbolAddress((void**)&pa, g_a);
    float* pb;  cudaGetSymbolAddress((void**)&pb, g_b);

    // Side stream + fork/join events: created lazily on the FIRST call, which
    // is the uncaptured correctness run (no creation during graph capture).
    static cudaStream_t sB = nullptr;
    static cudaEvent_t evRoot = nullptr, evGemm = nullptr;
    if (sB == nullptr) {
        cudaStreamCreateWithFlags(&sB, cudaStreamNonBlocking);
        cudaEventCreateWithFlags(&evRoot, cudaEventDisableTiming);
        cudaEventCreateWithFlags(&evGemm, cudaEventDisableTiming);
    }

    const int TB = 256;
    const int initN  = (N_NODES > NGRAPH * HID) ? N_NODES : NGRAPH * HID;
    const int nblkI  = (initN + TB - 1) / TB;
    const int nblkE  = (N_EDGES + TB - 1) / TB;
    const int nblkG  = (N_NODES + 63) / 64;
    const int nblkAg = (N_NODES + 15) / 16;

    // Fork: gemm1 (x,W1 only) runs on sB concurrently with the CSR build.
    cudaEventRecord(evRoot, 0);
    cudaStreamWaitEvent(sB, evRoot, 0);
    k_gemm_fused<F_INDIM, false><<<nblkG, TB, 0, sB>>>(x, W1, nullptr, pa);
    cudaEventRecord(evGemm, sB);

    // CSR build on the main (capture) stream.
    k_init   <<<nblkI, TB>>>();
    k_count  <<<nblkE, TB>>>(ei);
    k_scan1  <<<NSBLK, SBLK>>>(bat);     // + dinv + per-graph counts
    k_scan2  <<<1, SBLK>>>();
    k_scan3  <<<NSBLK, SBLK>>>();
    k_scatter<<<nblkE, TB>>>(ei);

    // Join: agg1 needs both gemm1 output and the CSR.
    cudaStreamWaitEvent(0, evGemm, 0);
    k_agg_csr<false><<<nblkAg, TB>>>(bat);

    // layer 2 (relu + b1 fused into gemm input; pool fused into agg)
    k_gemm_fused<HID, true><<<nblkG, TB>>>(pb, W2, b1, pa);
    k_agg_csr<true><<<nblkAg, TB>>>(bat);

    // linear head (b2 folded in)
    k_final<<<(NGRAPH * 32 + TB - 1) / TB, TB>>>(b2, Wout, bout, out);
}